// round 12
// baseline (speedup 1.0000x reference)
#include <cuda_runtime.h>
#include <cuda_bf16.h>
#include <math.h>

// Problem constants (fixed shapes from reference)
#define BATCH   4
#define NS      2048
#define NTOT    4096
#define KDIM    32
#define TILE    128
#define NTILES  (NTOT / TILE)                // 32
#define NTRI    (NTILES * (NTILES + 1) / 2)  // 528 upper-triangular tiles
#define NTHREADS 256
#define PREP_BLOCKS 64                        // blocks per batch (64 points each)
#define BF_STRIDE 40                          // bf16/row: 32 + 8 pad (80B) -> LDSM conflict-free

// Device-global scratch (allocation-free per harness rules)
__device__ double g_acc[BATCH];
__device__ float  g_sq[BATCH * NTOT];
__device__ float  g_pcol[BATCH][PREP_BLOCKS][KDIM];
__device__ float  g_psq[BATCH][PREP_BLOCKS];
__device__ int    g_done;
// Precomputed bf16 two-term split of all points (1 MB each; L2-resident)
__device__ __nv_bfloat16 g_hi[BATCH * NTOT * KDIM];
__device__ __nv_bfloat16 g_lo[BATCH * NTOT * KDIM];

__device__ __forceinline__ float ex2f(float x) {
    float r;
    asm("ex2.approx.ftz.f32 %0, %1;" : "=f"(r) : "f"(x));
    return r;
}
__device__ __forceinline__ unsigned int su32(const void* p) {
    return (unsigned int)__cvta_generic_to_shared(p);
}
__device__ __forceinline__ unsigned int packbf(float a, float b) {
    __nv_bfloat162 h(__float2bfloat16_rn(a), __float2bfloat16_rn(b));
    return *reinterpret_cast<unsigned int*>(&h);
}

// ---------------------------------------------------------------------------
// K_A: bf16 split + per-point sq norms + partial column/sq sums.
// grid = (PREP_BLOCKS, BATCH), 256 threads. Thread t: point = base + t/4,
// feature chunk c = t&3 covers k = 8c..8c+7. Block (0,0) also resets
// the accumulators (safe: no other prep block touches them).
// ---------------------------------------------------------------------------
__global__ void mmd_prep_a(const float* __restrict__ src,
                           const float* __restrict__ tgt) {
    const int b   = blockIdx.y;
    const int blk = blockIdx.x;
    const int tid = threadIdx.x;
    const int c   = tid & 3;

    if (b == 0 && blk == 0) {
        if (tid < BATCH) g_acc[tid] = 0.0;
        if (tid == BATCH) g_done = 0;
    }

    __shared__ float colacc[KDIM];
    __shared__ float blocksq;

    if (tid < KDIM) colacc[tid] = 0.0f;
    if (tid == 0) blocksq = 0.0f;
    __syncthreads();

    const int i = blk * 64 + (tid >> 2);
    const float* row = (i < NS)
        ? src + ((size_t)b * NS + i) * KDIM
        : tgt + ((size_t)b * NS + (i - NS)) * KDIM;
    float4 v0 = reinterpret_cast<const float4*>(row)[2 * c];
    float4 v1 = reinterpret_cast<const float4*>(row)[2 * c + 1];
    float col[8] = {v0.x, v0.y, v0.z, v0.w, v1.x, v1.y, v1.z, v1.w};

    // bf16 hi/lo split, stored as uint4 (8 bf16) per array
    float hi[8], lo[8];
    #pragma unroll
    for (int u = 0; u < 8; u++) {
        hi[u] = __bfloat162float(__float2bfloat16_rn(col[u]));
        lo[u] = col[u] - hi[u];
    }
    const size_t boff = (((size_t)b * NTOT + i) * KDIM + 8 * c) / 8;  // uint4 index
    reinterpret_cast<uint4*>(g_hi)[boff] =
        make_uint4(packbf(hi[0], hi[1]), packbf(hi[2], hi[3]),
                   packbf(hi[4], hi[5]), packbf(hi[6], hi[7]));
    reinterpret_cast<uint4*>(g_lo)[boff] =
        make_uint4(packbf(lo[0], lo[1]), packbf(lo[2], lo[3]),
                   packbf(lo[4], lo[5]), packbf(lo[6], lo[7]));

    float s = 0.0f;
    #pragma unroll
    for (int u = 0; u < 8; u++) s += col[u] * col[u];

    // Per-point sq norm: reduce over 4-thread group sharing this point
    float spt = s;
    spt += __shfl_xor_sync(0xffffffffu, spt, 1);
    spt += __shfl_xor_sync(0xffffffffu, spt, 2);
    if (c == 0) g_sq[b * NTOT + i] = spt;

    // Column sums: reduce over the 8 points in this warp (same c: stride 4)
    #pragma unroll
    for (int u = 0; u < 8; u++) {
        float x = col[u];
        x += __shfl_down_sync(0xffffffffu, x, 16);
        x += __shfl_down_sync(0xffffffffu, x, 8);
        x += __shfl_down_sync(0xffffffffu, x, 4);
        col[u] = x;
    }
    if ((tid & 31) < 4)
        #pragma unroll
        for (int u = 0; u < 8; u++)
            atomicAdd(&colacc[8 * c + u], col[u]);

    // Block sq total (full warp reduce of raw s)
    #pragma unroll
    for (int off = 16; off > 0; off >>= 1)
        s += __shfl_down_sync(0xffffffffu, s, off);
    if ((tid & 31) == 0) atomicAdd(&blocksq, s);

    __syncthreads();
    if (tid < KDIM) g_pcol[b][blk][tid] = colacc[tid];
    if (tid == 0)   g_psq[b][blk] = blocksq;
}

// ---------------------------------------------------------------------------
// mma.sync helpers (legacy warp MMA, bf16 -> fp32)
// ---------------------------------------------------------------------------
__device__ __forceinline__ void mma_bf16(float* c, const unsigned int* a,
                                         const unsigned int* bb) {
    asm volatile(
        "mma.sync.aligned.m16n8k16.row.col.f32.bf16.bf16.f32 "
        "{%0,%1,%2,%3}, {%4,%5,%6,%7}, {%8,%9}, {%0,%1,%2,%3};"
        : "+f"(c[0]), "+f"(c[1]), "+f"(c[2]), "+f"(c[3])
        : "r"(a[0]), "r"(a[1]), "r"(a[2]), "r"(a[3]), "r"(bb[0]), "r"(bb[1]));
}
__device__ __forceinline__ void ldsm_x4(unsigned int* r, unsigned int addr) {
    asm volatile("ldmatrix.sync.aligned.m8n8.x4.shared.b16 {%0,%1,%2,%3}, [%4];"
                 : "=r"(r[0]), "=r"(r[1]), "=r"(r[2]), "=r"(r[3]) : "r"(addr));
}

// ---------------------------------------------------------------------------
// K2: pairwise kernel (reverted to the measured-best 16x128 warp tiling).
// Triangular tiling; Gram via bf16-split tensor MMA (hi*hi + hi*lo + lo*hi).
// Tile LDGs are hoisted into registers ABOVE the in-block qlog reduction so
// L2 latency overlaps it; Ra/Rb are scaled at write time so no post-mainloop
// barrier is needed. grid = (NTRI, 1, BATCH).
// ---------------------------------------------------------------------------
__global__ __launch_bounds__(NTHREADS, 2)
void mmd_pairs(float* __restrict__ out) {
    const int b = blockIdx.z;
    const int t = blockIdx.x;
    int by = (int)((sqrtf(8.0f * (float)t + 1.0f) - 1.0f) * 0.5f);
    while ((by + 1) * (by + 2) / 2 <= t) by++;
    while (by * (by + 1) / 2 > t) by--;
    const int bx = t - by * (by + 1) / 2;

    const int tid  = threadIdx.x;
    const int lane = tid & 31;
    const int w    = tid >> 5;   // warp 0..7 -> rows 16w..16w+15

    const int i0 = bx * TILE;
    const int j0 = by * TILE;

    __shared__ __nv_bfloat16 A0[TILE * BF_STRIDE];
    __shared__ __nv_bfloat16 A1[TILE * BF_STRIDE];
    __shared__ __nv_bfloat16 B0[TILE * BF_STRIDE];
    __shared__ __nv_bfloat16 B1[TILE * BF_STRIDE];
    __shared__ float Ra[TILE];
    __shared__ float Rb[TILE];
    __shared__ float part[8][32];
    __shared__ float psqsh[64];
    __shared__ float red[8];
    __shared__ float qsh;

    // --- 1. Issue tile loads into registers (L2 latency overlaps reduction)
    const uint4* srcA0 = reinterpret_cast<const uint4*>(g_hi + ((size_t)b * NTOT + i0) * KDIM);
    const uint4* srcA1 = reinterpret_cast<const uint4*>(g_lo + ((size_t)b * NTOT + i0) * KDIM);
    const uint4* srcB0 = reinterpret_cast<const uint4*>(g_hi + ((size_t)b * NTOT + j0) * KDIM);
    const uint4* srcB1 = reinterpret_cast<const uint4*>(g_lo + ((size_t)b * NTOT + j0) * KDIM);
    uint4 ta0[2], ta1[2], tb0[2], tb1[2];
    #pragma unroll
    for (int it = 0; it < 2; it++) {
        int f = tid + NTHREADS * it;
        ta0[it] = srcA0[f];
        ta1[it] = srcA1[f];
        tb0[it] = srcB0[f];
        tb1[it] = srcB1[f];
    }
    float rav = (tid < TILE) ? g_sq[b * NTOT + i0 + tid]
                             : g_sq[b * NTOT + j0 + (tid - TILE)];

    // --- 2. In-block bandwidth reduction (overlapped with the LDGs above)
    {
        int k = tid & 31, grp = tid >> 5;
        float cs = 0.0f;
        #pragma unroll
        for (int u = 0; u < 8; u++) cs += g_pcol[b][8 * grp + u][k];
        part[grp][k] = cs;
        if (tid < 64) psqsh[tid] = g_psq[b][tid];
    }
    __syncthreads();
    if (tid < 32) {
        float cs = 0.0f;
        #pragma unroll
        for (int gg = 0; gg < 8; gg++) cs += part[gg][tid];
        float m2 = cs * cs;
        float ss = psqsh[tid] + psqsh[tid + 32];
        #pragma unroll
        for (int off = 16; off > 0; off >>= 1) {
            m2 += __shfl_xor_sync(0xffffffffu, m2, off);
            ss += __shfl_xor_sync(0xffffffffu, ss, off);
        }
        if (tid == 0) {
            const float n = (float)NTOT;
            float sumL2 = 2.0f * n * ss - 2.0f * m2;
            float bw = sumL2 / (n * n - n + 1e-8f);
            bw *= 0.25f;  // / KERNEL_MUL ** (KERNEL_NUM // 2)
            float q = 1.0f / (16.0f * bw);
            qsh = q * 1.4426950408889634f;  // qlog
        }
    }
    __syncthreads();
    const float qlog = qsh;
    const float nq = -qlog;

    // --- 3. Store tiles + pre-scaled Ra/Rb to shared
    #pragma unroll
    for (int it = 0; it < 2; it++) {
        int f = tid + NTHREADS * it;
        int p = f >> 2, q = f & 3;   // point, 8-elem chunk
        *reinterpret_cast<uint4*>(&A0[p * BF_STRIDE + q * 8]) = ta0[it];
        *reinterpret_cast<uint4*>(&A1[p * BF_STRIDE + q * 8]) = ta1[it];
        *reinterpret_cast<uint4*>(&B0[p * BF_STRIDE + q * 8]) = tb0[it];
        *reinterpret_cast<uint4*>(&B1[p * BF_STRIDE + q * 8]) = tb1[it];
    }
    if (tid < TILE) Ra[tid] = rav * nq;
    else            Rb[tid - TILE] = rav * nq;
    __syncthreads();

    // --- 4. Mainloop: each warp computes rows [16w,16w+16) x all 128 j.
    float acc[16][4];
    #pragma unroll
    for (int nt = 0; nt < 16; nt++)
        #pragma unroll
        for (int u = 0; u < 4; u++) acc[nt][u] = 0.0f;

    const int arow = 16 * w + (lane & 15);
    #pragma unroll
    for (int ks = 0; ks < 2; ks++) {
        const int k0 = 16 * ks;
        const int acol = k0 + ((lane >> 4) << 3);
        unsigned int a0[4], a1[4];
        ldsm_x4(a0, su32(&A0[arow * BF_STRIDE + acol]));
        ldsm_x4(a1, su32(&A1[arow * BF_STRIDE + acol]));
        const int brow = ((lane >> 4) << 3) + (lane & 7);
        const int bcol = k0 + (lane & 8);
        #pragma unroll
        for (int nt2 = 0; nt2 < 8; nt2++) {
            unsigned int bb0[4], bb1[4];
            ldsm_x4(bb0, su32(&B0[(16 * nt2 + brow) * BF_STRIDE + bcol]));
            ldsm_x4(bb1, su32(&B1[(16 * nt2 + brow) * BF_STRIDE + bcol]));
            mma_bf16(acc[2 * nt2],     a0, bb0);      // hi*hi
            mma_bf16(acc[2 * nt2],     a0, bb1);      // hi*lo
            mma_bf16(acc[2 * nt2],     a1, bb0);      // lo*hi
            mma_bf16(acc[2 * nt2 + 1], a0, bb0 + 2);
            mma_bf16(acc[2 * nt2 + 1], a0, bb1 + 2);
            mma_bf16(acc[2 * nt2 + 1], a1, bb0 + 2);
        }
    }

    // --- 5. Epilogue (no barrier needed: Ra/Rb published pre-mainloop).
    // D frag: rows r=16w+g, r+8 (g=lane>>2); cols j=8nt+2*(lane&3)+{0,1}.
    // arg = c2*dot - qlog*(sq_i+sq_j); e=2^arg, g4=2^(4*arg);
    // sum = fma(e,e,e) + fma(g4,g4,g4) + (g4^2)^2 = e+e2 + e4+e8 + e16.
    const float c2 = 2.0f * qlog;
    const int g = lane >> 2;
    const float nra0 = Ra[16 * w + g];
    const float nra1 = Ra[16 * w + g + 8];
    const int jb = 2 * (lane & 3);
    float tsA = 0.0f, tsB = 0.0f, tsC = 0.0f;
    #pragma unroll
    for (int nt = 0; nt < 16; nt++) {
        float2 nrb = *reinterpret_cast<const float2*>(&Rb[8 * nt + jb]);
        float args[4] = {
            fmaf(acc[nt][0], c2, nra0 + nrb.x),
            fmaf(acc[nt][1], c2, nra0 + nrb.y),
            fmaf(acc[nt][2], c2, nra1 + nrb.x),
            fmaf(acc[nt][3], c2, nra1 + nrb.y),
        };
        #pragma unroll
        for (int u = 0; u < 4; u++) {
            float e  = ex2f(args[u]);
            float g4 = ex2f(4.0f * args[u]);
            float g2 = g4 * g4;                 // e^8
            tsA += fmaf(e, e, e);               // e + e^2
            tsB += fmaf(g4, g4, g4);            // e^4 + e^8
            tsC = fmaf(g2, g2, tsC);            // e^16
        }
    }
    float tsum = (tsA + tsB) + tsC;

    // --- 6. Warp-shuffle reduction, then tiny cross-warp pass
    #pragma unroll
    for (int off = 16; off > 0; off >>= 1)
        tsum += __shfl_xor_sync(0xffffffffu, tsum, off);
    if (lane == 0) red[w] = tsum;
    __syncthreads();
    if (tid == 0) {
        float blocksum = 0.0f;
        #pragma unroll
        for (int u = 0; u < 8; u++) blocksum += red[u];
        double wgt = (bx == by) ? 1.0 : 2.0;
        double sgn = ((bx < NTILES / 2) == (by < NTILES / 2)) ? wgt : -wgt;
        atomicAdd(&g_acc[b], sgn * (double)blocksum);
        __threadfence();
        int v = atomicAdd(&g_done, 1);
        if (v == NTRI * BATCH - 1) {
            __threadfence();
            double scale = exp(1e-8) / ((double)NS * (double)NS);
            #pragma unroll
            for (int q = 0; q < BATCH; q++)
                out[q] = (float)(g_acc[q] * scale);
        }
    }
}

extern "C" void kernel_launch(void* const* d_in, const int* in_sizes, int n_in,
                              void* d_out, int out_size) {
    const float* src = (const float*)d_in[0];
    const float* tgt = (const float*)d_in[1];
    float* out = (float*)d_out;

    mmd_prep_a<<<dim3(PREP_BLOCKS, BATCH), 256>>>(src, tgt);
    mmd_pairs<<<dim3(NTRI, 1, BATCH), NTHREADS>>>(out);
}

// round 13
// speedup vs baseline: 1.6767x; 1.6767x over previous
#include <cuda_runtime.h>
#include <cuda_bf16.h>
#include <math.h>

// Problem constants (fixed shapes from reference)
#define BATCH   4
#define NS      2048
#define NTOT    4096
#define KDIM    32
#define TILE    128
#define NTILES  (NTOT / TILE)                // 32
#define NTRI    (NTILES * (NTILES + 1) / 2)  // 528 upper-triangular tiles
#define NTHREADS 256
#define PREP_BLOCKS 64                        // blocks per batch (64 points each)
#define BF_STRIDE 40                          // bf16/row: 32 + 8 pad (80B) -> LDSM conflict-free

// Device-global scratch (allocation-free per harness rules)
__device__ double g_acc[BATCH];
__device__ float  g_sq[BATCH * NTOT];
__device__ float  g_pcol[BATCH][PREP_BLOCKS][KDIM];
__device__ float  g_psq[BATCH][PREP_BLOCKS];
__device__ int    g_done;
// Precomputed bf16 two-term split of all points (1 MB each; L2-resident)
__device__ __nv_bfloat16 g_hi[BATCH * NTOT * KDIM];
__device__ __nv_bfloat16 g_lo[BATCH * NTOT * KDIM];

__device__ __forceinline__ float ex2f(float x) {
    float r;
    asm("ex2.approx.ftz.f32 %0, %1;" : "=f"(r) : "f"(x));
    return r;
}
__device__ __forceinline__ unsigned int su32(const void* p) {
    return (unsigned int)__cvta_generic_to_shared(p);
}
__device__ __forceinline__ unsigned int packbf(float a, float b) {
    __nv_bfloat162 h(__float2bfloat16_rn(a), __float2bfloat16_rn(b));
    return *reinterpret_cast<unsigned int*>(&h);
}

// ---------------------------------------------------------------------------
// K_A: bf16 split + per-point sq norms + partial column/sq sums.
// grid = (PREP_BLOCKS, BATCH), 256 threads. Thread t: point = base + t/4,
// feature chunk c = t&3 covers k = 8c..8c+7. Block (0,0) also resets
// the accumulators (safe: no other prep block touches them).
// ---------------------------------------------------------------------------
__global__ void mmd_prep_a(const float* __restrict__ src,
                           const float* __restrict__ tgt) {
    const int b   = blockIdx.y;
    const int blk = blockIdx.x;
    const int tid = threadIdx.x;
    const int c   = tid & 3;

    if (b == 0 && blk == 0) {
        if (tid < BATCH) g_acc[tid] = 0.0;
        if (tid == BATCH) g_done = 0;
    }

    __shared__ float colacc[KDIM];
    __shared__ float blocksq;

    if (tid < KDIM) colacc[tid] = 0.0f;
    if (tid == 0) blocksq = 0.0f;
    __syncthreads();

    const int i = blk * 64 + (tid >> 2);
    const float* row = (i < NS)
        ? src + ((size_t)b * NS + i) * KDIM
        : tgt + ((size_t)b * NS + (i - NS)) * KDIM;
    float4 v0 = reinterpret_cast<const float4*>(row)[2 * c];
    float4 v1 = reinterpret_cast<const float4*>(row)[2 * c + 1];
    float col[8] = {v0.x, v0.y, v0.z, v0.w, v1.x, v1.y, v1.z, v1.w};

    // bf16 hi/lo split, stored as uint4 (8 bf16) per array
    float hi[8], lo[8];
    #pragma unroll
    for (int u = 0; u < 8; u++) {
        hi[u] = __bfloat162float(__float2bfloat16_rn(col[u]));
        lo[u] = col[u] - hi[u];
    }
    const size_t boff = (((size_t)b * NTOT + i) * KDIM + 8 * c) / 8;  // uint4 index
    reinterpret_cast<uint4*>(g_hi)[boff] =
        make_uint4(packbf(hi[0], hi[1]), packbf(hi[2], hi[3]),
                   packbf(hi[4], hi[5]), packbf(hi[6], hi[7]));
    reinterpret_cast<uint4*>(g_lo)[boff] =
        make_uint4(packbf(lo[0], lo[1]), packbf(lo[2], lo[3]),
                   packbf(lo[4], lo[5]), packbf(lo[6], lo[7]));

    float s = 0.0f;
    #pragma unroll
    for (int u = 0; u < 8; u++) s += col[u] * col[u];

    // Per-point sq norm: reduce over 4-thread group sharing this point
    float spt = s;
    spt += __shfl_xor_sync(0xffffffffu, spt, 1);
    spt += __shfl_xor_sync(0xffffffffu, spt, 2);
    if (c == 0) g_sq[b * NTOT + i] = spt;

    // Column sums: reduce over the 8 points in this warp (same c: stride 4)
    #pragma unroll
    for (int u = 0; u < 8; u++) {
        float x = col[u];
        x += __shfl_down_sync(0xffffffffu, x, 16);
        x += __shfl_down_sync(0xffffffffu, x, 8);
        x += __shfl_down_sync(0xffffffffu, x, 4);
        col[u] = x;
    }
    if ((tid & 31) < 4)
        #pragma unroll
        for (int u = 0; u < 8; u++)
            atomicAdd(&colacc[8 * c + u], col[u]);

    // Block sq total (full warp reduce of raw s)
    #pragma unroll
    for (int off = 16; off > 0; off >>= 1)
        s += __shfl_down_sync(0xffffffffu, s, off);
    if ((tid & 31) == 0) atomicAdd(&blocksq, s);

    __syncthreads();
    if (tid < KDIM) g_pcol[b][blk][tid] = colacc[tid];
    if (tid == 0)   g_psq[b][blk] = blocksq;
}

// ---------------------------------------------------------------------------
// mma.sync helpers (legacy warp MMA, bf16 -> fp32)
// ---------------------------------------------------------------------------
__device__ __forceinline__ void mma_bf16(float* c, const unsigned int* a,
                                         const unsigned int* bb) {
    asm volatile(
        "mma.sync.aligned.m16n8k16.row.col.f32.bf16.bf16.f32 "
        "{%0,%1,%2,%3}, {%4,%5,%6,%7}, {%8,%9}, {%0,%1,%2,%3};"
        : "+f"(c[0]), "+f"(c[1]), "+f"(c[2]), "+f"(c[3])
        : "r"(a[0]), "r"(a[1]), "r"(a[2]), "r"(a[3]), "r"(bb[0]), "r"(bb[1]));
}
__device__ __forceinline__ void ldsm_x4(unsigned int* r, unsigned int addr) {
    asm volatile("ldmatrix.sync.aligned.m8n8.x4.shared.b16 {%0,%1,%2,%3}, [%4];"
                 : "=r"(r[0]), "=r"(r[1]), "=r"(r[2]), "=r"(r[3]) : "r"(addr));
}

// ---------------------------------------------------------------------------
// K2: pairwise kernel. 16x128 warp tile processed in 4 column-chunks of 32
// with the epilogue fused per chunk: acc shrinks 64 -> 16 regs, enabling
// 3 blocks/SM (24 resident warps vs 16). Triangular tiling; Gram via
// bf16-split tensor MMA (hi*hi + hi*lo + lo*hi). grid = (NTRI, 1, BATCH).
// ---------------------------------------------------------------------------
__global__ __launch_bounds__(NTHREADS, 3)
void mmd_pairs(float* __restrict__ out) {
    const int b = blockIdx.z;
    const int t = blockIdx.x;
    int by = (int)((sqrtf(8.0f * (float)t + 1.0f) - 1.0f) * 0.5f);
    while ((by + 1) * (by + 2) / 2 <= t) by++;
    while (by * (by + 1) / 2 > t) by--;
    const int bx = t - by * (by + 1) / 2;

    const int tid  = threadIdx.x;
    const int lane = tid & 31;
    const int w    = tid >> 5;   // warp 0..7 -> rows 16w..16w+15

    const int i0 = bx * TILE;
    const int j0 = by * TILE;

    __shared__ __nv_bfloat16 A0[TILE * BF_STRIDE];
    __shared__ __nv_bfloat16 A1[TILE * BF_STRIDE];
    __shared__ __nv_bfloat16 B0[TILE * BF_STRIDE];
    __shared__ __nv_bfloat16 B1[TILE * BF_STRIDE];
    __shared__ float Ra[TILE];
    __shared__ float Rb[TILE];
    __shared__ float part[8][32];
    __shared__ float psqsh[64];
    __shared__ float red[8];
    __shared__ float qsh;

    // --- 1. Issue tile loads into registers (L2 latency overlaps reduction)
    const uint4* srcA0 = reinterpret_cast<const uint4*>(g_hi + ((size_t)b * NTOT + i0) * KDIM);
    const uint4* srcA1 = reinterpret_cast<const uint4*>(g_lo + ((size_t)b * NTOT + i0) * KDIM);
    const uint4* srcB0 = reinterpret_cast<const uint4*>(g_hi + ((size_t)b * NTOT + j0) * KDIM);
    const uint4* srcB1 = reinterpret_cast<const uint4*>(g_lo + ((size_t)b * NTOT + j0) * KDIM);
    uint4 ta0[2], ta1[2], tb0[2], tb1[2];
    #pragma unroll
    for (int it = 0; it < 2; it++) {
        int f = tid + NTHREADS * it;
        ta0[it] = srcA0[f];
        ta1[it] = srcA1[f];
        tb0[it] = srcB0[f];
        tb1[it] = srcB1[f];
    }
    float rav = (tid < TILE) ? g_sq[b * NTOT + i0 + tid]
                             : g_sq[b * NTOT + j0 + (tid - TILE)];

    // --- 2. In-block bandwidth reduction (overlapped with the LDGs above)
    {
        int k = tid & 31, grp = tid >> 5;
        float cs = 0.0f;
        #pragma unroll
        for (int u = 0; u < 8; u++) cs += g_pcol[b][8 * grp + u][k];
        part[grp][k] = cs;
        if (tid < 64) psqsh[tid] = g_psq[b][tid];
    }
    __syncthreads();
    if (tid < 32) {
        float cs = 0.0f;
        #pragma unroll
        for (int gg = 0; gg < 8; gg++) cs += part[gg][tid];
        float m2 = cs * cs;
        float ss = psqsh[tid] + psqsh[tid + 32];
        #pragma unroll
        for (int off = 16; off > 0; off >>= 1) {
            m2 += __shfl_xor_sync(0xffffffffu, m2, off);
            ss += __shfl_xor_sync(0xffffffffu, ss, off);
        }
        if (tid == 0) {
            const float n = (float)NTOT;
            float sumL2 = 2.0f * n * ss - 2.0f * m2;
            float bw = sumL2 / (n * n - n + 1e-8f);
            bw *= 0.25f;  // / KERNEL_MUL ** (KERNEL_NUM // 2)
            float q = 1.0f / (16.0f * bw);
            qsh = q * 1.4426950408889634f;  // qlog
        }
    }
    __syncthreads();
    const float qlog = qsh;
    const float nq = -qlog;

    // --- 3. Store tiles + pre-scaled Ra/Rb to shared
    #pragma unroll
    for (int it = 0; it < 2; it++) {
        int f = tid + NTHREADS * it;
        int p = f >> 2, q = f & 3;   // point, 8-elem chunk
        *reinterpret_cast<uint4*>(&A0[p * BF_STRIDE + q * 8]) = ta0[it];
        *reinterpret_cast<uint4*>(&A1[p * BF_STRIDE + q * 8]) = ta1[it];
        *reinterpret_cast<uint4*>(&B0[p * BF_STRIDE + q * 8]) = tb0[it];
        *reinterpret_cast<uint4*>(&B1[p * BF_STRIDE + q * 8]) = tb1[it];
    }
    if (tid < TILE) Ra[tid] = rav * nq;
    else            Rb[tid - TILE] = rav * nq;
    __syncthreads();

    // --- 4. Preload A fragments for both k-steps (16 regs, reused all chunks)
    unsigned int a0[2][4], a1[2][4];
    const int arow = 16 * w + (lane & 15);
    #pragma unroll
    for (int ks = 0; ks < 2; ks++) {
        const int acol = 16 * ks + ((lane >> 4) << 3);
        ldsm_x4(a0[ks], su32(&A0[arow * BF_STRIDE + acol]));
        ldsm_x4(a1[ks], su32(&A1[arow * BF_STRIDE + acol]));
    }

    // --- 5. Chunked main loop: 4 chunks x 32 cols; MMA + fused epilogue.
    const float c2 = 2.0f * qlog;
    const int g = lane >> 2;
    const float nra0 = Ra[16 * w + g];
    const float nra1 = Ra[16 * w + g + 8];
    const int jb = 2 * (lane & 3);
    const int brow = ((lane >> 4) << 3) + (lane & 7);

    float tsA = 0.0f, tsB = 0.0f, tsC = 0.0f;
    #pragma unroll
    for (int ch = 0; ch < 4; ch++) {
        float acc[4][4];
        #pragma unroll
        for (int nt = 0; nt < 4; nt++)
            #pragma unroll
            for (int u = 0; u < 4; u++) acc[nt][u] = 0.0f;

        #pragma unroll
        for (int ks = 0; ks < 2; ks++) {
            const int bcol = 16 * ks + (lane & 8);
            #pragma unroll
            for (int p = 0; p < 2; p++) {     // 16-col group within chunk
                const int bbase = 32 * ch + 16 * p + brow;
                unsigned int bb0[4], bb1[4];
                ldsm_x4(bb0, su32(&B0[bbase * BF_STRIDE + bcol]));
                ldsm_x4(bb1, su32(&B1[bbase * BF_STRIDE + bcol]));
                mma_bf16(acc[2 * p],     a0[ks], bb0);      // hi*hi
                mma_bf16(acc[2 * p],     a0[ks], bb1);      // hi*lo
                mma_bf16(acc[2 * p],     a1[ks], bb0);      // lo*hi
                mma_bf16(acc[2 * p + 1], a0[ks], bb0 + 2);
                mma_bf16(acc[2 * p + 1], a0[ks], bb1 + 2);
                mma_bf16(acc[2 * p + 1], a1[ks], bb0 + 2);
            }
        }

        // Fused epilogue for this chunk's 32 columns.
        // acc[nt]: rows 16w+g, +8; cols 32ch+8nt+2*(lane&3)+{0,1}.
        // arg = c2*dot - qlog*(sq_i+sq_j); e=2^arg, g4=2^(4*arg);
        // sum = fma(e,e,e) + fma(g4,g4,g4) + (g4^2)^2 = e+e2 + e4+e8 + e16.
        #pragma unroll
        for (int nt = 0; nt < 4; nt++) {
            float2 nrb = *reinterpret_cast<const float2*>(&Rb[32 * ch + 8 * nt + jb]);
            float args[4] = {
                fmaf(acc[nt][0], c2, nra0 + nrb.x),
                fmaf(acc[nt][1], c2, nra0 + nrb.y),
                fmaf(acc[nt][2], c2, nra1 + nrb.x),
                fmaf(acc[nt][3], c2, nra1 + nrb.y),
            };
            #pragma unroll
            for (int u = 0; u < 4; u++) {
                float e  = ex2f(args[u]);
                float g4 = ex2f(4.0f * args[u]);
                float g2 = g4 * g4;                 // e^8
                tsA += fmaf(e, e, e);               // e + e^2
                tsB += fmaf(g4, g4, g4);            // e^4 + e^8
                tsC = fmaf(g2, g2, tsC);            // e^16
            }
        }
    }
    float tsum = (tsA + tsB) + tsC;

    // --- 6. Warp-shuffle reduction, then tiny cross-warp pass
    #pragma unroll
    for (int off = 16; off > 0; off >>= 1)
        tsum += __shfl_xor_sync(0xffffffffu, tsum, off);
    if (lane == 0) red[w] = tsum;
    __syncthreads();
    if (tid == 0) {
        float blocksum = 0.0f;
        #pragma unroll
        for (int u = 0; u < 8; u++) blocksum += red[u];
        double wgt = (bx == by) ? 1.0 : 2.0;
        double sgn = ((bx < NTILES / 2) == (by < NTILES / 2)) ? wgt : -wgt;
        atomicAdd(&g_acc[b], sgn * (double)blocksum);
        __threadfence();
        int v = atomicAdd(&g_done, 1);
        if (v == NTRI * BATCH - 1) {
            __threadfence();
            double scale = exp(1e-8) / ((double)NS * (double)NS);
            #pragma unroll
            for (int q = 0; q < BATCH; q++)
                out[q] = (float)(g_acc[q] * scale);
        }
    }
}

extern "C" void kernel_launch(void* const* d_in, const int* in_sizes, int n_in,
                              void* d_out, int out_size) {
    const float* src = (const float*)d_in[0];
    const float* tgt = (const float*)d_in[1];
    float* out = (float*)d_out;

    mmd_prep_a<<<dim3(PREP_BLOCKS, BATCH), 256>>>(src, tgt);
    mmd_pairs<<<dim3(NTRI, 1, BATCH), NTHREADS>>>(out);
}

// round 14
// speedup vs baseline: 1.7671x; 1.0539x over previous
#include <cuda_runtime.h>
#include <cuda_bf16.h>
#include <math.h>

// Problem constants (fixed shapes from reference)
#define BATCH   4
#define NS      2048
#define NTOT    4096
#define KDIM    32
#define TILE    128
#define NTILES  (NTOT / TILE)                // 32
#define NTRI    (NTILES * (NTILES + 1) / 2)  // 528 upper-triangular tiles
#define NTHREADS 256
#define PREP_BLOCKS 64                        // blocks per batch (64 points each)
#define BF_STRIDE 40                          // bf16/row: 32 + 8 pad (80B) -> LDSM conflict-free

// Device-global scratch (allocation-free per harness rules)
__device__ double g_acc[BATCH];
__device__ float  g_sq[BATCH * NTOT];
__device__ float  g_pcol[BATCH][PREP_BLOCKS][KDIM];
__device__ float  g_psq[BATCH][PREP_BLOCKS];
__device__ int    g_done;
// Precomputed bf16 two-term split of all points (1 MB each; L2-resident)
__device__ __nv_bfloat16 g_hi[BATCH * NTOT * KDIM];
__device__ __nv_bfloat16 g_lo[BATCH * NTOT * KDIM];

__device__ __forceinline__ float ex2f(float x) {
    float r;
    asm("ex2.approx.ftz.f32 %0, %1;" : "=f"(r) : "f"(x));
    return r;
}
__device__ __forceinline__ unsigned int su32(const void* p) {
    return (unsigned int)__cvta_generic_to_shared(p);
}
__device__ __forceinline__ unsigned int packbf(float a, float b) {
    __nv_bfloat162 h(__float2bfloat16_rn(a), __float2bfloat16_rn(b));
    return *reinterpret_cast<unsigned int*>(&h);
}

// ---------------------------------------------------------------------------
// K_A: bf16 split + per-point sq norms + partial column/sq sums.
// grid = (PREP_BLOCKS, BATCH), 256 threads. Thread t: point = base + t/4,
// feature chunk c = t&3 covers k = 8c..8c+7. Block (0,0) also resets
// the accumulators (safe: no other prep block touches them).
// ---------------------------------------------------------------------------
__global__ void mmd_prep_a(const float* __restrict__ src,
                           const float* __restrict__ tgt) {
    const int b   = blockIdx.y;
    const int blk = blockIdx.x;
    const int tid = threadIdx.x;
    const int c   = tid & 3;

    if (b == 0 && blk == 0) {
        if (tid < BATCH) g_acc[tid] = 0.0;
        if (tid == BATCH) g_done = 0;
    }

    __shared__ float colacc[KDIM];
    __shared__ float blocksq;

    if (tid < KDIM) colacc[tid] = 0.0f;
    if (tid == 0) blocksq = 0.0f;
    __syncthreads();

    const int i = blk * 64 + (tid >> 2);
    const float* row = (i < NS)
        ? src + ((size_t)b * NS + i) * KDIM
        : tgt + ((size_t)b * NS + (i - NS)) * KDIM;
    float4 v0 = reinterpret_cast<const float4*>(row)[2 * c];
    float4 v1 = reinterpret_cast<const float4*>(row)[2 * c + 1];
    float col[8] = {v0.x, v0.y, v0.z, v0.w, v1.x, v1.y, v1.z, v1.w};

    // bf16 hi/lo split, stored as uint4 (8 bf16) per array
    float hi[8], lo[8];
    #pragma unroll
    for (int u = 0; u < 8; u++) {
        hi[u] = __bfloat162float(__float2bfloat16_rn(col[u]));
        lo[u] = col[u] - hi[u];
    }
    const size_t boff = (((size_t)b * NTOT + i) * KDIM + 8 * c) / 8;  // uint4 index
    reinterpret_cast<uint4*>(g_hi)[boff] =
        make_uint4(packbf(hi[0], hi[1]), packbf(hi[2], hi[3]),
                   packbf(hi[4], hi[5]), packbf(hi[6], hi[7]));
    reinterpret_cast<uint4*>(g_lo)[boff] =
        make_uint4(packbf(lo[0], lo[1]), packbf(lo[2], lo[3]),
                   packbf(lo[4], lo[5]), packbf(lo[6], lo[7]));

    float s = 0.0f;
    #pragma unroll
    for (int u = 0; u < 8; u++) s += col[u] * col[u];

    // Per-point sq norm: reduce over 4-thread group sharing this point
    float spt = s;
    spt += __shfl_xor_sync(0xffffffffu, spt, 1);
    spt += __shfl_xor_sync(0xffffffffu, spt, 2);
    if (c == 0) g_sq[b * NTOT + i] = spt;

    // Column sums: reduce over the 8 points in this warp (same c: stride 4)
    #pragma unroll
    for (int u = 0; u < 8; u++) {
        float x = col[u];
        x += __shfl_down_sync(0xffffffffu, x, 16);
        x += __shfl_down_sync(0xffffffffu, x, 8);
        x += __shfl_down_sync(0xffffffffu, x, 4);
        col[u] = x;
    }
    if ((tid & 31) < 4)
        #pragma unroll
        for (int u = 0; u < 8; u++)
            atomicAdd(&colacc[8 * c + u], col[u]);

    // Block sq total (full warp reduce of raw s)
    #pragma unroll
    for (int off = 16; off > 0; off >>= 1)
        s += __shfl_down_sync(0xffffffffu, s, off);
    if ((tid & 31) == 0) atomicAdd(&blocksq, s);

    __syncthreads();
    if (tid < KDIM) g_pcol[b][blk][tid] = colacc[tid];
    if (tid == 0)   g_psq[b][blk] = blocksq;
}

// ---------------------------------------------------------------------------
// mma.sync helpers (legacy warp MMA, bf16 -> fp32)
// ---------------------------------------------------------------------------
__device__ __forceinline__ void mma_bf16(float* c, const unsigned int* a,
                                         const unsigned int* bb) {
    asm volatile(
        "mma.sync.aligned.m16n8k16.row.col.f32.bf16.bf16.f32 "
        "{%0,%1,%2,%3}, {%4,%5,%6,%7}, {%8,%9}, {%0,%1,%2,%3};"
        : "+f"(c[0]), "+f"(c[1]), "+f"(c[2]), "+f"(c[3])
        : "r"(a[0]), "r"(a[1]), "r"(a[2]), "r"(a[3]), "r"(bb[0]), "r"(bb[1]));
}
__device__ __forceinline__ void ldsm_x4(unsigned int* r, unsigned int addr) {
    asm volatile("ldmatrix.sync.aligned.m8n8.x4.shared.b16 {%0,%1,%2,%3}, [%4];"
                 : "=r"(r[0]), "=r"(r[1]), "=r"(r[2]), "=r"(r[3]) : "r"(addr));
}

// ---------------------------------------------------------------------------
// K2: pairwise kernel. 16x128 warp tile processed in 4 column-chunks of 32
// with the epilogue fused per chunk (acc = 16 regs). Direct gmem->smem
// prologue (no register staging) to fit 64 regs -> 4 blocks/SM.
// Triangular tiling; Gram via bf16-split tensor MMA (hi*hi + hi*lo + lo*hi).
// grid = (NTRI, 1, BATCH).
// ---------------------------------------------------------------------------
__global__ __launch_bounds__(NTHREADS, 4)
void mmd_pairs(float* __restrict__ out) {
    const int b = blockIdx.z;
    const int t = blockIdx.x;
    int by = (int)((sqrtf(8.0f * (float)t + 1.0f) - 1.0f) * 0.5f);
    while ((by + 1) * (by + 2) / 2 <= t) by++;
    while (by * (by + 1) / 2 > t) by--;
    const int bx = t - by * (by + 1) / 2;

    const int tid  = threadIdx.x;
    const int lane = tid & 31;
    const int w    = tid >> 5;   // warp 0..7 -> rows 16w..16w+15

    const int i0 = bx * TILE;
    const int j0 = by * TILE;

    __shared__ __nv_bfloat16 A0[TILE * BF_STRIDE];
    __shared__ __nv_bfloat16 A1[TILE * BF_STRIDE];
    __shared__ __nv_bfloat16 B0[TILE * BF_STRIDE];
    __shared__ __nv_bfloat16 B1[TILE * BF_STRIDE];
    __shared__ float Ra[TILE];
    __shared__ float Rb[TILE];
    __shared__ float part[8][32];
    __shared__ float psqsh[64];
    __shared__ float red[8];
    __shared__ float qsh;

    // --- 1. Tile copies gmem->smem (direct; inter-block overlap hides L2 lat)
    const uint4* srcA0 = reinterpret_cast<const uint4*>(g_hi + ((size_t)b * NTOT + i0) * KDIM);
    const uint4* srcA1 = reinterpret_cast<const uint4*>(g_lo + ((size_t)b * NTOT + i0) * KDIM);
    const uint4* srcB0 = reinterpret_cast<const uint4*>(g_hi + ((size_t)b * NTOT + j0) * KDIM);
    const uint4* srcB1 = reinterpret_cast<const uint4*>(g_lo + ((size_t)b * NTOT + j0) * KDIM);
    #pragma unroll
    for (int it = 0; it < 2; it++) {
        int f = tid + NTHREADS * it;
        int p = f >> 2, q = f & 3;   // point, 8-elem chunk
        *reinterpret_cast<uint4*>(&A0[p * BF_STRIDE + q * 8]) = srcA0[f];
        *reinterpret_cast<uint4*>(&A1[p * BF_STRIDE + q * 8]) = srcA1[f];
        *reinterpret_cast<uint4*>(&B0[p * BF_STRIDE + q * 8]) = srcB0[f];
        *reinterpret_cast<uint4*>(&B1[p * BF_STRIDE + q * 8]) = srcB1[f];
    }
    float rav = (tid < TILE) ? g_sq[b * NTOT + i0 + tid]
                             : g_sq[b * NTOT + j0 + (tid - TILE)];

    // --- 2. In-block bandwidth reduction
    {
        int k = tid & 31, grp = tid >> 5;
        float cs = 0.0f;
        #pragma unroll
        for (int u = 0; u < 8; u++) cs += g_pcol[b][8 * grp + u][k];
        part[grp][k] = cs;
        if (tid < 64) psqsh[tid] = g_psq[b][tid];
    }
    __syncthreads();
    if (tid < 32) {
        float cs = 0.0f;
        #pragma unroll
        for (int gg = 0; gg < 8; gg++) cs += part[gg][tid];
        float m2 = cs * cs;
        float ss = psqsh[tid] + psqsh[tid + 32];
        #pragma unroll
        for (int off = 16; off > 0; off >>= 1) {
            m2 += __shfl_xor_sync(0xffffffffu, m2, off);
            ss += __shfl_xor_sync(0xffffffffu, ss, off);
        }
        if (tid == 0) {
            const float n = (float)NTOT;
            float sumL2 = 2.0f * n * ss - 2.0f * m2;
            float bw = sumL2 / (n * n - n + 1e-8f);
            bw *= 0.25f;  // / KERNEL_MUL ** (KERNEL_NUM // 2)
            float q = 1.0f / (16.0f * bw);
            qsh = q * 1.4426950408889634f;  // qlog
        }
    }
    __syncthreads();
    const float qlog = qsh;
    const float nq = -qlog;

    // --- 3. Pre-scaled Ra/Rb to shared
    if (tid < TILE) Ra[tid] = rav * nq;
    else            Rb[tid - TILE] = rav * nq;
    __syncthreads();

    // --- 4. Preload A fragments for both k-steps (16 regs, reused all chunks)
    unsigned int a0[2][4], a1[2][4];
    const int arow = 16 * w + (lane & 15);
    #pragma unroll
    for (int ks = 0; ks < 2; ks++) {
        const int acol = 16 * ks + ((lane >> 4) << 3);
        ldsm_x4(a0[ks], su32(&A0[arow * BF_STRIDE + acol]));
        ldsm_x4(a1[ks], su32(&A1[arow * BF_STRIDE + acol]));
    }

    // --- 5. Chunked main loop: 4 chunks x 32 cols; MMA + fused epilogue.
    const float c2 = 2.0f * qlog;
    const int g = lane >> 2;
    const float nra0 = Ra[16 * w + g];
    const float nra1 = Ra[16 * w + g + 8];
    const int jb = 2 * (lane & 3);
    const int brow = ((lane >> 4) << 3) + (lane & 7);

    float tsA = 0.0f, tsB = 0.0f, tsC = 0.0f;
    #pragma unroll
    for (int ch = 0; ch < 4; ch++) {
        float acc[4][4];
        #pragma unroll
        for (int nt = 0; nt < 4; nt++)
            #pragma unroll
            for (int u = 0; u < 4; u++) acc[nt][u] = 0.0f;

        #pragma unroll
        for (int ks = 0; ks < 2; ks++) {
            const int bcol = 16 * ks + (lane & 8);
            #pragma unroll
            for (int p = 0; p < 2; p++) {     // 16-col group within chunk
                const int bbase = 32 * ch + 16 * p + brow;
                unsigned int bb0[4], bb1[4];
                ldsm_x4(bb0, su32(&B0[bbase * BF_STRIDE + bcol]));
                ldsm_x4(bb1, su32(&B1[bbase * BF_STRIDE + bcol]));
                mma_bf16(acc[2 * p],     a0[ks], bb0);      // hi*hi
                mma_bf16(acc[2 * p],     a0[ks], bb1);      // hi*lo
                mma_bf16(acc[2 * p],     a1[ks], bb0);      // lo*hi
                mma_bf16(acc[2 * p + 1], a0[ks], bb0 + 2);
                mma_bf16(acc[2 * p + 1], a0[ks], bb1 + 2);
                mma_bf16(acc[2 * p + 1], a1[ks], bb0 + 2);
            }
        }

        // Fused epilogue for this chunk's 32 columns.
        // acc[nt]: rows 16w+g, +8; cols 32ch+8nt+2*(lane&3)+{0,1}.
        // arg = c2*dot - qlog*(sq_i+sq_j); e=2^arg, g4=2^(4*arg);
        // sum = fma(e,e,e) + fma(g4,g4,g4) + (g4^2)^2 = e+e2 + e4+e8 + e16.
        #pragma unroll
        for (int nt = 0; nt < 4; nt++) {
            float2 nrb = *reinterpret_cast<const float2*>(&Rb[32 * ch + 8 * nt + jb]);
            float args[4] = {
                fmaf(acc[nt][0], c2, nra0 + nrb.x),
                fmaf(acc[nt][1], c2, nra0 + nrb.y),
                fmaf(acc[nt][2], c2, nra1 + nrb.x),
                fmaf(acc[nt][3], c2, nra1 + nrb.y),
            };
            #pragma unroll
            for (int u = 0; u < 4; u++) {
                float e  = ex2f(args[u]);
                float g4 = ex2f(4.0f * args[u]);
                float g2 = g4 * g4;                 // e^8
                tsA += fmaf(e, e, e);               // e + e^2
                tsB += fmaf(g4, g4, g4);            // e^4 + e^8
                tsC = fmaf(g2, g2, tsC);            // e^16
            }
        }
    }
    float tsum = (tsA + tsB) + tsC;

    // --- 6. Warp-shuffle reduction, then tiny cross-warp pass
    #pragma unroll
    for (int off = 16; off > 0; off >>= 1)
        tsum += __shfl_xor_sync(0xffffffffu, tsum, off);
    if (lane == 0) red[w] = tsum;
    __syncthreads();
    if (tid == 0) {
        float blocksum = 0.0f;
        #pragma unroll
        for (int u = 0; u < 8; u++) blocksum += red[u];
        double wgt = (bx == by) ? 1.0 : 2.0;
        double sgn = ((bx < NTILES / 2) == (by < NTILES / 2)) ? wgt : -wgt;
        atomicAdd(&g_acc[b], sgn * (double)blocksum);
        __threadfence();
        int v = atomicAdd(&g_done, 1);
        if (v == NTRI * BATCH - 1) {
            __threadfence();
            double scale = exp(1e-8) / ((double)NS * (double)NS);
            #pragma unroll
            for (int q = 0; q < BATCH; q++)
                out[q] = (float)(g_acc[q] * scale);
        }
    }
}

extern "C" void kernel_launch(void* const* d_in, const int* in_sizes, int n_in,
                              void* d_out, int out_size) {
    const float* src = (const float*)d_in[0];
    const float* tgt = (const float*)d_in[1];
    float* out = (float*)d_out;

    mmd_prep_a<<<dim3(PREP_BLOCKS, BATCH), 256>>>(src, tgt);
    mmd_pairs<<<dim3(NTRI, 1, BATCH), NTHREADS>>>(out);
}